// round 1
// baseline (speedup 1.0000x reference)
#include <cuda_runtime.h>

// Problem constants
#define EMB   1024
#define NH    16
#define HD    64
#define BATCH 4
#define SEQ   1024
#define SCALING 0.3952847075210474f   // (64*0.1)^-0.5

// Scratch (device globals: no allocation allowed)
__device__ float g_qkv[BATCH * SEQ * 3 * EMB];   // [4096, 3072]
__device__ float g_att[BATCH * SEQ * EMB];       // [4096, 1024]

// ---------------------------------------------------------------------------
// GEMM: C[M,N] = A[M,K] * B[N,K]^T + bias[N]     (both operands K-contiguous)
// 128x128 block, BK=16, 256 threads, 8x8 per thread (split 4+4 halves)
// ---------------------------------------------------------------------------
#define BM 128
#define BN 128
#define BK 16

__global__ __launch_bounds__(256)
void gemm_nt(const float* __restrict__ A, const float* __restrict__ Bw,
             const float* __restrict__ bias, float* __restrict__ C,
             int M, int N, int K)
{
    __shared__ float As[BK][BM + 4];
    __shared__ float Bs[BK][BN + 4];

    const int t  = threadIdx.x;
    const int tx = t & 15;          // N dim
    const int ty = t >> 4;          // M dim
    const int bm = blockIdx.y * BM;
    const int bn = blockIdx.x * BN;

    const int lr = t >> 2;          // 0..63 : row within tile
    const int lk = (t & 3) << 2;    // 0,4,8,12 : k offset

    const float* Aptr = A + (size_t)(bm + lr) * K + lk;
    const float* Bptr = Bw + (size_t)(bn + lr) * K + lk;

    float acc[8][8];
#pragma unroll
    for (int i = 0; i < 8; i++)
#pragma unroll
        for (int j = 0; j < 8; j++) acc[i][j] = 0.f;

    // prefetch first tile
    float4 pa0 = *(const float4*)(Aptr);
    float4 pa1 = *(const float4*)(Aptr + (size_t)64 * K);
    float4 pb0 = *(const float4*)(Bptr);
    float4 pb1 = *(const float4*)(Bptr + (size_t)64 * K);

    for (int k0 = 0; k0 < K; k0 += BK) {
        // store current tile (transposed) into smem
        As[lk + 0][lr] = pa0.x; As[lk + 1][lr] = pa0.y;
        As[lk + 2][lr] = pa0.z; As[lk + 3][lr] = pa0.w;
        As[lk + 0][lr + 64] = pa1.x; As[lk + 1][lr + 64] = pa1.y;
        As[lk + 2][lr + 64] = pa1.z; As[lk + 3][lr + 64] = pa1.w;
        Bs[lk + 0][lr] = pb0.x; Bs[lk + 1][lr] = pb0.y;
        Bs[lk + 2][lr] = pb0.z; Bs[lk + 3][lr] = pb0.w;
        Bs[lk + 0][lr + 64] = pb1.x; Bs[lk + 1][lr + 64] = pb1.y;
        Bs[lk + 2][lr + 64] = pb1.z; Bs[lk + 3][lr + 64] = pb1.w;
        __syncthreads();

        // prefetch next tile into registers (overlaps with compute)
        int kn = k0 + BK;
        if (kn < K) {
            pa0 = *(const float4*)(Aptr + kn);
            pa1 = *(const float4*)(Aptr + (size_t)64 * K + kn);
            pb0 = *(const float4*)(Bptr + kn);
            pb1 = *(const float4*)(Bptr + (size_t)64 * K + kn);
        }

#pragma unroll
        for (int k = 0; k < BK; k++) {
            float4 av0 = *(const float4*)&As[k][ty * 4];
            float4 av1 = *(const float4*)&As[k][64 + ty * 4];
            float4 bv0 = *(const float4*)&Bs[k][tx * 4];
            float4 bv1 = *(const float4*)&Bs[k][64 + tx * 4];
            float a[8] = {av0.x, av0.y, av0.z, av0.w, av1.x, av1.y, av1.z, av1.w};
            float b[8] = {bv0.x, bv0.y, bv0.z, bv0.w, bv1.x, bv1.y, bv1.z, bv1.w};
#pragma unroll
            for (int i = 0; i < 8; i++)
#pragma unroll
                for (int j = 0; j < 8; j++)
                    acc[i][j] += a[i] * b[j];
        }
        __syncthreads();
    }

    // epilogue
#pragma unroll
    for (int ih = 0; ih < 2; ih++) {
#pragma unroll
        for (int i = 0; i < 4; i++) {
            int row = bm + ih * 64 + ty * 4 + i;
#pragma unroll
            for (int jh = 0; jh < 2; jh++) {
                int col = bn + jh * 64 + tx * 4;
                float4 r;
                r.x = acc[ih * 4 + i][jh * 4 + 0] + bias[col + 0];
                r.y = acc[ih * 4 + i][jh * 4 + 1] + bias[col + 1];
                r.z = acc[ih * 4 + i][jh * 4 + 2] + bias[col + 2];
                r.w = acc[ih * 4 + i][jh * 4 + 3] + bias[col + 3];
                *(float4*)&C[(size_t)row * N + col] = r;
            }
        }
    }
}

// ---------------------------------------------------------------------------
// Fused flash attention with additive bias + key padding mask.
// One block per (b, h, 64-row q tile). 256 threads (16x16), 4x4 microtiles.
// Smem: Q[64][68], K[64][68] (aliased by P after scores), V[64][68].
// ---------------------------------------------------------------------------
#define BR 64
#define BC 64
#define QS 68   // smem row stride (conflict-free float4 reads across rows)

__global__ __launch_bounds__(256)
void attn_kernel(const float* __restrict__ bias,
                 const unsigned char* __restrict__ mask,
                 float* __restrict__ out,
                 const float* __restrict__ qkv)
{
    extern __shared__ float sm[];
    float* Qs = sm;                 // BR*QS
    float* Ks = sm + BR * QS;       // BC*QS (also holds P after scores)
    float* Vs = sm + 2 * BR * QS;   // BC*QS

    const int t  = threadIdx.x;
    const int tx = t & 15;
    const int ty = t >> 4;
    const int qt = blockIdx.x;
    const int h  = blockIdx.y;
    const int b  = blockIdx.z;
    const int qbase = qt * BR;

    const float* qkv_q = qkv + (size_t)b * SEQ * 3 * EMB + h * HD;
    const float* qkv_k = qkv_q + EMB;
    const float* qkv_v = qkv_q + 2 * EMB;
    const float* brow  = bias + (size_t)(b * NH + h) * SEQ * SEQ;
    const unsigned char* mrow = mask + (size_t)b * SEQ;

    // load Q tile
    for (int idx = t; idx < BR * 16; idx += 256) {
        int r = idx >> 4, dq = (idx & 15) << 2;
        *(float4*)&Qs[r * QS + dq] =
            *(const float4*)(qkv_q + (size_t)(qbase + r) * 3 * EMB + dq);
    }

    float Oacc[4][4];
#pragma unroll
    for (int i = 0; i < 4; i++)
#pragma unroll
        for (int j = 0; j < 4; j++) Oacc[i][j] = 0.f;
    float m_prev[4] = {-1e30f, -1e30f, -1e30f, -1e30f};
    float l_run[4]  = {0.f, 0.f, 0.f, 0.f};

    for (int kb = 0; kb < SEQ; kb += BC) {
        // load K, V tiles
        for (int idx = t; idx < BC * 16; idx += 256) {
            int r = idx >> 4, dq = (idx & 15) << 2;
            *(float4*)&Ks[r * QS + dq] =
                *(const float4*)(qkv_k + (size_t)(kb + r) * 3 * EMB + dq);
            *(float4*)&Vs[r * QS + dq] =
                *(const float4*)(qkv_v + (size_t)(kb + r) * 3 * EMB + dq);
        }
        __syncthreads();

        // S = Q K^T (4x4 per thread)
        float s[4][4];
#pragma unroll
        for (int i = 0; i < 4; i++)
#pragma unroll
            for (int j = 0; j < 4; j++) s[i][j] = 0.f;

#pragma unroll 8
        for (int d = 0; d < HD; d += 4) {
            float4 qv[4], kv[4];
#pragma unroll
            for (int i = 0; i < 4; i++)
                qv[i] = *(const float4*)&Qs[(ty * 4 + i) * QS + d];
#pragma unroll
            for (int j = 0; j < 4; j++)
                kv[j] = *(const float4*)&Ks[(tx * 4 + j) * QS + d];
#pragma unroll
            for (int i = 0; i < 4; i++)
#pragma unroll
                for (int j = 0; j < 4; j++)
                    s[i][j] += qv[i].x * kv[j].x + qv[i].y * kv[j].y +
                               qv[i].z * kv[j].z + qv[i].w * kv[j].w;
        }

        // scale + bias + mask
        uchar4 m4 = *(const uchar4*)(mrow + kb + tx * 4);
#pragma unroll
        for (int i = 0; i < 4; i++) {
            float4 bv = *(const float4*)&brow[(size_t)(qbase + ty * 4 + i) * SEQ + kb + tx * 4];
            s[i][0] = m4.x ? -1e30f : (s[i][0] * SCALING + bv.x);
            s[i][1] = m4.y ? -1e30f : (s[i][1] * SCALING + bv.y);
            s[i][2] = m4.z ? -1e30f : (s[i][2] * SCALING + bv.z);
            s[i][3] = m4.w ? -1e30f : (s[i][3] * SCALING + bv.w);
        }

        // online softmax (rows reduce across the 16 tx lanes)
#pragma unroll
        for (int i = 0; i < 4; i++) {
            float mx = fmaxf(fmaxf(s[i][0], s[i][1]), fmaxf(s[i][2], s[i][3]));
#pragma unroll
            for (int off = 8; off >= 1; off >>= 1)
                mx = fmaxf(mx, __shfl_xor_sync(0xffffffffu, mx, off));
            float mnew  = fmaxf(m_prev[i], mx);
            float scale = __expf(m_prev[i] - mnew);
            m_prev[i] = mnew;
            float ps = 0.f;
#pragma unroll
            for (int j = 0; j < 4; j++) {
                s[i][j] = __expf(s[i][j] - mnew);
                ps += s[i][j];
            }
#pragma unroll
            for (int off = 8; off >= 1; off >>= 1)
                ps += __shfl_xor_sync(0xffffffffu, ps, off);
            l_run[i] = l_run[i] * scale + ps;
#pragma unroll
            for (int j = 0; j < 4; j++) Oacc[i][j] *= scale;
        }

        __syncthreads();   // everyone done reading K
        // write P into the K buffer
#pragma unroll
        for (int i = 0; i < 4; i++)
            *(float4*)&Ks[(ty * 4 + i) * QS + tx * 4] =
                make_float4(s[i][0], s[i][1], s[i][2], s[i][3]);
        __syncthreads();

        // O += P V
#pragma unroll 4
        for (int kk = 0; kk < BC; kk += 4) {
            float4 v0 = *(const float4*)&Vs[(kk + 0) * QS + tx * 4];
            float4 v1 = *(const float4*)&Vs[(kk + 1) * QS + tx * 4];
            float4 v2 = *(const float4*)&Vs[(kk + 2) * QS + tx * 4];
            float4 v3 = *(const float4*)&Vs[(kk + 3) * QS + tx * 4];
#pragma unroll
            for (int i = 0; i < 4; i++) {
                float4 p = *(const float4*)&Ks[(ty * 4 + i) * QS + kk];
                Oacc[i][0] += p.x * v0.x + p.y * v1.x + p.z * v2.x + p.w * v3.x;
                Oacc[i][1] += p.x * v0.y + p.y * v1.y + p.z * v2.y + p.w * v3.y;
                Oacc[i][2] += p.x * v0.z + p.y * v1.z + p.z * v2.z + p.w * v3.z;
                Oacc[i][3] += p.x * v0.w + p.y * v1.w + p.z * v2.w + p.w * v3.w;
            }
        }
        __syncthreads();   // before next tile overwrites K/V
    }

    // finalize + store
#pragma unroll
    for (int i = 0; i < 4; i++) {
        float inv = 1.f / l_run[i];
        size_t row = (size_t)b * SEQ + qbase + ty * 4 + i;
        float4 r = make_float4(Oacc[i][0] * inv, Oacc[i][1] * inv,
                               Oacc[i][2] * inv, Oacc[i][3] * inv);
        *(float4*)&out[row * EMB + h * HD + tx * 4] = r;
    }
}

// ---------------------------------------------------------------------------
extern "C" void kernel_launch(void* const* d_in, const int* in_sizes, int n_in,
                              void* d_out, int out_size)
{
    const float* query         = (const float*)d_in[0];
    const unsigned char* maskp = (const unsigned char*)d_in[1];
    const float* attn_bias     = (const float*)d_in[2];
    const float* Wqkv          = (const float*)d_in[3];
    const float* bqkv          = (const float*)d_in[4];
    const float* Wo            = (const float*)d_in[5];
    const float* bo            = (const float*)d_in[6];
    float* out                 = (float*)d_out;

    float *qkv, *att;
    cudaGetSymbolAddress((void**)&qkv, g_qkv);
    cudaGetSymbolAddress((void**)&att, g_att);

    // 1) QKV projection: [4096,1024] x [3072,1024]^T -> [4096,3072]
    {
        dim3 grid(3 * EMB / BN, (BATCH * SEQ) / BM);
        gemm_nt<<<grid, 256>>>(query, Wqkv, bqkv, qkv, BATCH * SEQ, 3 * EMB, EMB);
    }

    // 2) fused attention
    {
        size_t smem = (size_t)3 * BR * QS * sizeof(float);   // 52224 B
        cudaFuncSetAttribute(attn_kernel,
                             cudaFuncAttributeMaxDynamicSharedMemorySize, (int)smem);
        dim3 grid(SEQ / BR, NH, BATCH);
        attn_kernel<<<grid, 256, smem>>>(attn_bias, maskp, att, qkv);
    }

    // 3) output projection: [4096,1024] x [1024,1024]^T -> [4096,1024]
    {
        dim3 grid(EMB / BN, (BATCH * SEQ) / BM);
        gemm_nt<<<grid, 256>>>(att, Wo, bo, out, BATCH * SEQ, EMB, EMB);
    }
}

// round 2
// speedup vs baseline: 1.3109x; 1.3109x over previous
#include <cuda_runtime.h>
#include <cuda_bf16.h>
#include <cstdint>

// Problem constants
#define EMB   1024
#define NH    16
#define HD    64
#define BATCH 4
#define SEQ   1024
#define MTOT  (BATCH*SEQ)
#define SCALING 0.3952847075210474f   // (64*0.1)^-0.5

// Scratch (device globals: no allocation allowed)
__device__ float g_qkv[MTOT * 3 * EMB];   // [4096, 3072]
__device__ float g_att[MTOT * EMB];       // [4096, 1024]
__device__ __nv_bfloat16 g_A_hi[MTOT * EMB];
__device__ __nv_bfloat16 g_A_lo[MTOT * EMB];
__device__ __nv_bfloat16 g_W1_hi[3 * EMB * EMB];
__device__ __nv_bfloat16 g_W1_lo[3 * EMB * EMB];
__device__ __nv_bfloat16 g_W2_hi[EMB * EMB];
__device__ __nv_bfloat16 g_W2_lo[EMB * EMB];
__device__ __nv_bfloat16 g_att_hi[MTOT * EMB];
__device__ __nv_bfloat16 g_att_lo[MTOT * EMB];

// ---------------------------------------------------------------------------
// f32 -> bf16 (hi, lo) split:  x ~= hi + lo, residual ~2^-18 * |x|
// ---------------------------------------------------------------------------
__global__ __launch_bounds__(256)
void split_kernel(const float* __restrict__ in,
                  __nv_bfloat16* __restrict__ hi,
                  __nv_bfloat16* __restrict__ lo, int n)
{
    int i = (blockIdx.x * blockDim.x + threadIdx.x) * 4;
    if (i >= n) return;
    float4 v = *(const float4*)(in + i);
    float f[4] = {v.x, v.y, v.z, v.w};
    __nv_bfloat16 h[4], l[4];
#pragma unroll
    for (int j = 0; j < 4; j++) {
        h[j] = __float2bfloat16(f[j]);
        l[j] = __float2bfloat16(f[j] - __bfloat162float(h[j]));
    }
    *(uint2*)(hi + i) = *(const uint2*)h;
    *(uint2*)(lo + i) = *(const uint2*)l;
}

// ---------------------------------------------------------------------------
// Tensor-core GEMM:  C[M,N] = A[M,K] * B[N,K]^T + bias[N]
// A, B given as bf16 (hi, lo) pairs; product = hihi + hilo + lohi (fp32 acc).
// 128x128 tile, BK=32, 256 threads (8 warps: 4m x 2n), warp tile 32m x 64n.
// cp.async double buffering, ldmatrix fragment loads, mma.sync m16n8k16.
// ---------------------------------------------------------------------------
#define AST   40            // smem row stride in halves (80B: conflict-free)
#define STG_H (128 * AST)   // halves per matrix per stage

#define LDSM4(r, addr) \
    asm volatile("ldmatrix.sync.aligned.m8n8.x4.shared.b16 {%0,%1,%2,%3}, [%4];" \
                 : "=r"((r)[0]), "=r"((r)[1]), "=r"((r)[2]), "=r"((r)[3]) : "r"(addr))

#define MMA_BF16(d, a, b) \
    asm volatile("mma.sync.aligned.m16n8k16.row.col.f32.bf16.bf16.f32 " \
                 "{%0,%1,%2,%3},{%4,%5,%6,%7},{%8,%9},{%0,%1,%2,%3};" \
                 : "+f"((d)[0]), "+f"((d)[1]), "+f"((d)[2]), "+f"((d)[3]) \
                 : "r"((a)[0]), "r"((a)[1]), "r"((a)[2]), "r"((a)[3]), \
                   "r"((b)[0]), "r"((b)[1]))

__device__ __forceinline__ void cp16(uint32_t s, const void* g) {
    asm volatile("cp.async.cg.shared.global [%0], [%1], 16;" :: "r"(s), "l"(g));
}

__global__ __launch_bounds__(256)
void gemm_mma(const __nv_bfloat16* __restrict__ Ah,
              const __nv_bfloat16* __restrict__ Al,
              const __nv_bfloat16* __restrict__ Bh,
              const __nv_bfloat16* __restrict__ Bl,
              const float* __restrict__ bias,
              float* __restrict__ C, int M, int N, int K)
{
    extern __shared__ __align__(16) __nv_bfloat16 smem_b[];
    const uint32_t sm_base = (uint32_t)__cvta_generic_to_shared(smem_b);

    const int t    = threadIdx.x;
    const int lane = t & 31;
    const int w    = t >> 5;
    const int wm   = w & 3;     // m-warp index (4)
    const int wn   = w >> 2;    // n-warp index (2)
    const int bm   = blockIdx.y * 128;
    const int bn   = blockIdx.x * 128;
    const int nk   = K >> 5;

    float acc[2][8][4];
#pragma unroll
    for (int mi = 0; mi < 2; mi++)
#pragma unroll
        for (int ni = 0; ni < 8; ni++)
#pragma unroll
            for (int q = 0; q < 4; q++) acc[mi][ni][q] = 0.f;

    // cp.async chunk coords for this thread (2 chunks per matrix)
    const int c0row = (t + 0)   >> 2, c0k = ((t + 0)   & 3) * 8;
    const int c1row = (t + 256) >> 2, c1k = ((t + 256) & 3) * 8;

    const __nv_bfloat16* gp[4] = {Ah, Al, Bh, Bl};

    auto issue = [&](int stage, int k0) {
#pragma unroll
        for (int m = 0; m < 4; m++) {
            int base = (m < 2) ? bm : bn;
            const __nv_bfloat16* g = gp[m];
            uint32_t so = sm_base + (uint32_t)(stage * 4 + m) * STG_H * 2;
            cp16(so + (uint32_t)(c0row * AST + c0k) * 2,
                 g + (size_t)(base + c0row) * K + k0 + c0k);
            cp16(so + (uint32_t)(c1row * AST + c1k) * 2,
                 g + (size_t)(base + c1row) * K + k0 + c1k);
        }
        asm volatile("cp.async.commit_group;");
    };

    issue(0, 0);

    for (int kt = 0; kt < nk; kt++) {
        if (kt + 1 < nk) {
            issue((kt + 1) & 1, (kt + 1) << 5);
            asm volatile("cp.async.wait_group 1;");
        } else {
            asm volatile("cp.async.wait_group 0;");
        }
        __syncthreads();

        const int stage = kt & 1;
        const uint32_t bAh = sm_base + (uint32_t)(stage * 4 + 0) * STG_H * 2;
        const uint32_t bAl = sm_base + (uint32_t)(stage * 4 + 1) * STG_H * 2;
        const uint32_t bBh = sm_base + (uint32_t)(stage * 4 + 2) * STG_H * 2;
        const uint32_t bBl = sm_base + (uint32_t)(stage * 4 + 3) * STG_H * 2;

#pragma unroll
        for (int ks = 0; ks < 2; ks++) {
            uint32_t ah[2][4], al[2][4], bh[8][2], bl[8][2];

            const int arow = wm * 32 + (lane & 15);
            const int acol = ks * 16 + (lane >> 4) * 8;
#pragma unroll
            for (int mi = 0; mi < 2; mi++) {
                uint32_t off = (uint32_t)((arow + mi * 16) * AST + acol) * 2;
                LDSM4(ah[mi], bAh + off);
                LDSM4(al[mi], bAl + off);
            }

            const int brow = wn * 64 + (lane >> 4) * 8 + (lane & 7);
            const int bcol = ks * 16 + ((lane >> 3) & 1) * 8;
#pragma unroll
            for (int ni2 = 0; ni2 < 4; ni2++) {
                uint32_t off = (uint32_t)((brow + ni2 * 16) * AST + bcol) * 2;
                uint32_t r[4];
                LDSM4(r, bBh + off);
                bh[ni2 * 2][0] = r[0]; bh[ni2 * 2][1] = r[1];
                bh[ni2 * 2 + 1][0] = r[2]; bh[ni2 * 2 + 1][1] = r[3];
                LDSM4(r, bBl + off);
                bl[ni2 * 2][0] = r[0]; bl[ni2 * 2][1] = r[1];
                bl[ni2 * 2 + 1][0] = r[2]; bl[ni2 * 2 + 1][1] = r[3];
            }

#pragma unroll
            for (int mi = 0; mi < 2; mi++)
#pragma unroll
                for (int ni = 0; ni < 8; ni++) {
                    MMA_BF16(acc[mi][ni], ah[mi], bh[ni]);   // hi*hi
                    MMA_BF16(acc[mi][ni], al[mi], bh[ni]);   // lo*hi
                    MMA_BF16(acc[mi][ni], ah[mi], bl[ni]);   // hi*lo
                }
        }
        __syncthreads();
    }

    // epilogue: add bias, store fp32
#pragma unroll
    for (int mi = 0; mi < 2; mi++) {
        const int r0 = bm + wm * 32 + mi * 16 + (lane >> 2);
#pragma unroll
        for (int ni = 0; ni < 8; ni++) {
            const int col = bn + wn * 64 + ni * 8 + (lane & 3) * 2;
            float bx = bias[col], by = bias[col + 1];
            float2 v0 = make_float2(acc[mi][ni][0] + bx, acc[mi][ni][1] + by);
            float2 v1 = make_float2(acc[mi][ni][2] + bx, acc[mi][ni][3] + by);
            *(float2*)&C[(size_t)r0 * N + col] = v0;
            *(float2*)&C[(size_t)(r0 + 8) * N + col] = v1;
        }
    }
}

// ---------------------------------------------------------------------------
// Fused flash attention with additive bias + key padding mask (unchanged).
// ---------------------------------------------------------------------------
#define BR 64
#define BC 64
#define QS 68

__global__ __launch_bounds__(256)
void attn_kernel(const float* __restrict__ bias,
                 const unsigned char* __restrict__ mask,
                 float* __restrict__ out,
                 const float* __restrict__ qkv)
{
    extern __shared__ float sm[];
    float* Qs = sm;
    float* Ks = sm + BR * QS;
    float* Vs = sm + 2 * BR * QS;

    const int t  = threadIdx.x;
    const int tx = t & 15;
    const int ty = t >> 4;
    const int qt = blockIdx.x;
    const int h  = blockIdx.y;
    const int b  = blockIdx.z;
    const int qbase = qt * BR;

    const float* qkv_q = qkv + (size_t)b * SEQ * 3 * EMB + h * HD;
    const float* qkv_k = qkv_q + EMB;
    const float* qkv_v = qkv_q + 2 * EMB;
    const float* brow  = bias + (size_t)(b * NH + h) * SEQ * SEQ;
    const unsigned char* mrow = mask + (size_t)b * SEQ;

    for (int idx = t; idx < BR * 16; idx += 256) {
        int r = idx >> 4, dq = (idx & 15) << 2;
        *(float4*)&Qs[r * QS + dq] =
            *(const float4*)(qkv_q + (size_t)(qbase + r) * 3 * EMB + dq);
    }

    float Oacc[4][4];
#pragma unroll
    for (int i = 0; i < 4; i++)
#pragma unroll
        for (int j = 0; j < 4; j++) Oacc[i][j] = 0.f;
    float m_prev[4] = {-1e30f, -1e30f, -1e30f, -1e30f};
    float l_run[4]  = {0.f, 0.f, 0.f, 0.f};

    for (int kb = 0; kb < SEQ; kb += BC) {
        for (int idx = t; idx < BC * 16; idx += 256) {
            int r = idx >> 4, dq = (idx & 15) << 2;
            *(float4*)&Ks[r * QS + dq] =
                *(const float4*)(qkv_k + (size_t)(kb + r) * 3 * EMB + dq);
            *(float4*)&Vs[r * QS + dq] =
                *(const float4*)(qkv_v + (size_t)(kb + r) * 3 * EMB + dq);
        }
        __syncthreads();

        float s[4][4];
#pragma unroll
        for (int i = 0; i < 4; i++)
#pragma unroll
            for (int j = 0; j < 4; j++) s[i][j] = 0.f;

#pragma unroll 8
        for (int d = 0; d < HD; d += 4) {
            float4 qv[4], kv[4];
#pragma unroll
            for (int i = 0; i < 4; i++)
                qv[i] = *(const float4*)&Qs[(ty * 4 + i) * QS + d];
#pragma unroll
            for (int j = 0; j < 4; j++)
                kv[j] = *(const float4*)&Ks[(tx * 4 + j) * QS + d];
#pragma unroll
            for (int i = 0; i < 4; i++)
#pragma unroll
                for (int j = 0; j < 4; j++)
                    s[i][j] += qv[i].x * kv[j].x + qv[i].y * kv[j].y +
                               qv[i].z * kv[j].z + qv[i].w * kv[j].w;
        }

        uchar4 m4 = *(const uchar4*)(mrow + kb + tx * 4);
#pragma unroll
        for (int i = 0; i < 4; i++) {
            float4 bv = *(const float4*)&brow[(size_t)(qbase + ty * 4 + i) * SEQ + kb + tx * 4];
            s[i][0] = m4.x ? -1e30f : (s[i][0] * SCALING + bv.x);
            s[i][1] = m4.y ? -1e30f : (s[i][1] * SCALING + bv.y);
            s[i][2] = m4.z ? -1e30f : (s[i][2] * SCALING + bv.z);
            s[i][3] = m4.w ? -1e30f : (s[i][3] * SCALING + bv.w);
        }

#pragma unroll
        for (int i = 0; i < 4; i++) {
            float mx = fmaxf(fmaxf(s[i][0], s[i][1]), fmaxf(s[i][2], s[i][3]));
#pragma unroll
            for (int off = 8; off >= 1; off >>= 1)
                mx = fmaxf(mx, __shfl_xor_sync(0xffffffffu, mx, off));
            float mnew  = fmaxf(m_prev[i], mx);
            float scale = __expf(m_prev[i] - mnew);
            m_prev[i] = mnew;
            float ps = 0.f;
#pragma unroll
            for (int j = 0; j < 4; j++) {
                s[i][j] = __expf(s[i][j] - mnew);
                ps += s[i][j];
            }
#pragma unroll
            for (int off = 8; off >= 1; off >>= 1)
                ps += __shfl_xor_sync(0xffffffffu, ps, off);
            l_run[i] = l_run[i] * scale + ps;
#pragma unroll
            for (int j = 0; j < 4; j++) Oacc[i][j] *= scale;
        }

        __syncthreads();
#pragma unroll
        for (int i = 0; i < 4; i++)
            *(float4*)&Ks[(ty * 4 + i) * QS + tx * 4] =
                make_float4(s[i][0], s[i][1], s[i][2], s[i][3]);
        __syncthreads();

#pragma unroll 4
        for (int kk = 0; kk < BC; kk += 4) {
            float4 v0 = *(const float4*)&Vs[(kk + 0) * QS + tx * 4];
            float4 v1 = *(const float4*)&Vs[(kk + 1) * QS + tx * 4];
            float4 v2 = *(const float4*)&Vs[(kk + 2) * QS + tx * 4];
            float4 v3 = *(const float4*)&Vs[(kk + 3) * QS + tx * 4];
#pragma unroll
            for (int i = 0; i < 4; i++) {
                float4 p = *(const float4*)&Ks[(ty * 4 + i) * QS + kk];
                Oacc[i][0] += p.x * v0.x + p.y * v1.x + p.z * v2.x + p.w * v3.x;
                Oacc[i][1] += p.x * v0.y + p.y * v1.y + p.z * v2.y + p.w * v3.y;
                Oacc[i][2] += p.x * v0.z + p.y * v1.z + p.z * v2.z + p.w * v3.z;
                Oacc[i][3] += p.x * v0.w + p.y * v1.w + p.z * v2.w + p.w * v3.w;
            }
        }
        __syncthreads();
    }

#pragma unroll
    for (int i = 0; i < 4; i++) {
        float inv = 1.f / l_run[i];
        size_t row = (size_t)b * SEQ + qbase + ty * 4 + i;
        float4 r = make_float4(Oacc[i][0] * inv, Oacc[i][1] * inv,
                               Oacc[i][2] * inv, Oacc[i][3] * inv);
        *(float4*)&out[row * EMB + h * HD + tx * 4] = r;
    }
}

// ---------------------------------------------------------------------------
extern "C" void kernel_launch(void* const* d_in, const int* in_sizes, int n_in,
                              void* d_out, int out_size)
{
    const float* query         = (const float*)d_in[0];
    const unsigned char* maskp = (const unsigned char*)d_in[1];
    const float* attn_bias     = (const float*)d_in[2];
    const float* Wqkv          = (const float*)d_in[3];
    const float* bqkv          = (const float*)d_in[4];
    const float* Wo            = (const float*)d_in[5];
    const float* bo            = (const float*)d_in[6];
    float* out                 = (float*)d_out;

    float *qkv, *att;
    __nv_bfloat16 *Ahi, *Alo, *W1hi, *W1lo, *W2hi, *W2lo, *Thi, *Tlo;
    cudaGetSymbolAddress((void**)&qkv,  g_qkv);
    cudaGetSymbolAddress((void**)&att,  g_att);
    cudaGetSymbolAddress((void**)&Ahi,  g_A_hi);
    cudaGetSymbolAddress((void**)&Alo,  g_A_lo);
    cudaGetSymbolAddress((void**)&W1hi, g_W1_hi);
    cudaGetSymbolAddress((void**)&W1lo, g_W1_lo);
    cudaGetSymbolAddress((void**)&W2hi, g_W2_hi);
    cudaGetSymbolAddress((void**)&W2lo, g_W2_lo);
    cudaGetSymbolAddress((void**)&Thi,  g_att_hi);
    cudaGetSymbolAddress((void**)&Tlo,  g_att_lo);

    const size_t gemm_smem = 8 * (size_t)STG_H * 2;   // 81920 B
    cudaFuncSetAttribute(gemm_mma,
                         cudaFuncAttributeMaxDynamicSharedMemorySize, (int)gemm_smem);
    const size_t attn_smem = (size_t)3 * BR * QS * sizeof(float);
    cudaFuncSetAttribute(attn_kernel,
                         cudaFuncAttributeMaxDynamicSharedMemorySize, (int)attn_smem);

    // 0) split inputs + weights into bf16 (hi, lo)
    split_kernel<<<(MTOT * EMB) / 1024, 256>>>(query, Ahi, Alo, MTOT * EMB);
    split_kernel<<<(3 * EMB * EMB) / 1024, 256>>>(Wqkv, W1hi, W1lo, 3 * EMB * EMB);
    split_kernel<<<(EMB * EMB) / 1024, 256>>>(Wo, W2hi, W2lo, EMB * EMB);

    // 1) QKV projection: [4096,1024] x [3072,1024]^T -> [4096,3072]
    {
        dim3 grid(3 * EMB / 128, MTOT / 128);
        gemm_mma<<<grid, 256, gemm_smem>>>(Ahi, Alo, W1hi, W1lo, bqkv, qkv,
                                           MTOT, 3 * EMB, EMB);
    }

    // 2) fused attention
    {
        dim3 grid(SEQ / BR, NH, BATCH);
        attn_kernel<<<grid, 256, attn_smem>>>(attn_bias, maskp, att, qkv);
    }

    // 3) split attention output, then output projection
    split_kernel<<<(MTOT * EMB) / 1024, 256>>>(att, Thi, Tlo, MTOT * EMB);
    {
        dim3 grid(EMB / 128, MTOT / 128);
        gemm_mma<<<grid, 256, gemm_smem>>>(Thi, Tlo, W2hi, W2lo, bo, out,
                                           MTOT, EMB, EMB);
    }
}

// round 3
// speedup vs baseline: 2.4998x; 1.9070x over previous
#include <cuda_runtime.h>
#include <cuda_bf16.h>
#include <cstdint>

// Problem constants
#define EMB   1024
#define NH    16
#define HD    64
#define BATCH 4
#define SEQ   1024
#define MTOT  (BATCH*SEQ)
#define SCALING 0.3952847075210474f   // (64*0.1)^-0.5
#define NEG   (-1e30f)

// Scratch (device globals: no allocation allowed)
__device__ float g_qkv[MTOT * 3 * EMB];   // [4096, 3072]
__device__ float g_att[MTOT * EMB];       // [4096, 1024]
__device__ __nv_bfloat16 g_A_hi[MTOT * EMB];
__device__ __nv_bfloat16 g_A_lo[MTOT * EMB];
__device__ __nv_bfloat16 g_W1_hi[3 * EMB * EMB];
__device__ __nv_bfloat16 g_W1_lo[3 * EMB * EMB];
__device__ __nv_bfloat16 g_W2_hi[EMB * EMB];
__device__ __nv_bfloat16 g_W2_lo[EMB * EMB];
__device__ __nv_bfloat16 g_att_hi[MTOT * EMB];
__device__ __nv_bfloat16 g_att_lo[MTOT * EMB];
// head-major [b, h, s, 64] bf16 hi/lo for attention
__device__ __nv_bfloat16 g_Qh[MTOT * EMB];
__device__ __nv_bfloat16 g_Ql[MTOT * EMB];
__device__ __nv_bfloat16 g_Kh[MTOT * EMB];
__device__ __nv_bfloat16 g_Kl[MTOT * EMB];
__device__ __nv_bfloat16 g_Vh[MTOT * EMB];
__device__ __nv_bfloat16 g_Vl[MTOT * EMB];

// ---------------------------------------------------------------------------
// PTX helpers
// ---------------------------------------------------------------------------
#define LDSM4(r, addr) \
    asm volatile("ldmatrix.sync.aligned.m8n8.x4.shared.b16 {%0,%1,%2,%3}, [%4];" \
                 : "=r"((r)[0]), "=r"((r)[1]), "=r"((r)[2]), "=r"((r)[3]) : "r"(addr))

#define LDSM4T(r, addr) \
    asm volatile("ldmatrix.sync.aligned.m8n8.x4.trans.shared.b16 {%0,%1,%2,%3}, [%4];" \
                 : "=r"((r)[0]), "=r"((r)[1]), "=r"((r)[2]), "=r"((r)[3]) : "r"(addr))

#define MMA_BF16(d, a, b) \
    asm volatile("mma.sync.aligned.m16n8k16.row.col.f32.bf16.bf16.f32 " \
                 "{%0,%1,%2,%3},{%4,%5,%6,%7},{%8,%9},{%0,%1,%2,%3};" \
                 : "+f"((d)[0]), "+f"((d)[1]), "+f"((d)[2]), "+f"((d)[3]) \
                 : "r"((a)[0]), "r"((a)[1]), "r"((a)[2]), "r"((a)[3]), \
                   "r"((b)[0]), "r"((b)[1]))

__device__ __forceinline__ void cp16(uint32_t s, const void* g) {
    asm volatile("cp.async.cg.shared.global [%0], [%1], 16;" :: "r"(s), "l"(g));
}

// pack {lo, hi} floats into bf16x2 register (lo -> low half)
__device__ __forceinline__ uint32_t packbf(float lo, float hi) {
    uint32_t r;
    asm("cvt.rn.bf16x2.f32 %0, %1, %2;" : "=r"(r) : "f"(hi), "f"(lo));
    return r;
}
// residual pack: (orig - bf16(orig)) for both halves
__device__ __forceinline__ uint32_t residpack(uint32_t ph, float lo, float hi) {
    float h_lo = __uint_as_float(ph << 16);
    float h_hi = __uint_as_float(ph & 0xffff0000u);
    return packbf(lo - h_lo, hi - h_hi);
}

// ---------------------------------------------------------------------------
// f32 -> bf16 (hi, lo) split
// ---------------------------------------------------------------------------
__global__ __launch_bounds__(256)
void split_kernel(const float* __restrict__ in,
                  __nv_bfloat16* __restrict__ hi,
                  __nv_bfloat16* __restrict__ lo, int n)
{
    int i = (blockIdx.x * blockDim.x + threadIdx.x) * 4;
    if (i >= n) return;
    float4 v = *(const float4*)(in + i);
    float f[4] = {v.x, v.y, v.z, v.w};
    __nv_bfloat16 h[4], l[4];
#pragma unroll
    for (int j = 0; j < 4; j++) {
        h[j] = __float2bfloat16(f[j]);
        l[j] = __float2bfloat16(f[j] - __bfloat162float(h[j]));
    }
    *(uint2*)(hi + i) = *(const uint2*)h;
    *(uint2*)(lo + i) = *(const uint2*)l;
}

// ---------------------------------------------------------------------------
// qkv (f32 [4096][3072]) -> head-major bf16 hi/lo [b,h,s,64]; Q scaled.
// blockIdx.y: 0=q, 1=k, 2=v
// ---------------------------------------------------------------------------
__global__ __launch_bounds__(256)
void qkv_split(const float* __restrict__ qkv,
               __nv_bfloat16* __restrict__ Qh, __nv_bfloat16* __restrict__ Ql,
               __nv_bfloat16* __restrict__ Kh, __nv_bfloat16* __restrict__ Kl,
               __nv_bfloat16* __restrict__ Vh, __nv_bfloat16* __restrict__ Vl)
{
    int m = blockIdx.y;
    int i = (blockIdx.x * 256 + threadIdx.x) * 4;
    int row = i >> 10, col = i & 1023;
    float4 v = *(const float4*)(qkv + (size_t)row * 3072 + m * 1024 + col);
    if (m == 0) { v.x *= SCALING; v.y *= SCALING; v.z *= SCALING; v.w *= SCALING; }
    int bb = row >> 10, s = row & 1023, hh = col >> 6, d = col & 63;
    size_t o = (((size_t)(bb * NH + hh)) * SEQ + s) * HD + d;
    __nv_bfloat16* hi = (m == 0) ? Qh : (m == 1) ? Kh : Vh;
    __nv_bfloat16* lo = (m == 0) ? Ql : (m == 1) ? Kl : Vl;
    float f[4] = {v.x, v.y, v.z, v.w};
    __nv_bfloat16 hb4[4], lb4[4];
#pragma unroll
    for (int j = 0; j < 4; j++) {
        hb4[j] = __float2bfloat16(f[j]);
        lb4[j] = __float2bfloat16(f[j] - __bfloat162float(hb4[j]));
    }
    *(uint2*)(hi + o) = *(const uint2*)hb4;
    *(uint2*)(lo + o) = *(const uint2*)lb4;
}

// ---------------------------------------------------------------------------
// Tensor-core GEMM (from R2): C[M,N] = A[M,K]*B[N,K]^T + bias[N], 3-term split
// ---------------------------------------------------------------------------
#define AST   40
#define STG_H (128 * AST)

__global__ __launch_bounds__(256)
void gemm_mma(const __nv_bfloat16* __restrict__ Ah,
              const __nv_bfloat16* __restrict__ Al,
              const __nv_bfloat16* __restrict__ Bh,
              const __nv_bfloat16* __restrict__ Bl,
              const float* __restrict__ bias,
              float* __restrict__ C, int M, int N, int K)
{
    extern __shared__ __align__(16) __nv_bfloat16 smem_b[];
    const uint32_t sm_base = (uint32_t)__cvta_generic_to_shared(smem_b);

    const int t    = threadIdx.x;
    const int lane = t & 31;
    const int w    = t >> 5;
    const int wm   = w & 3;
    const int wn   = w >> 2;
    const int bm   = blockIdx.y * 128;
    const int bn   = blockIdx.x * 128;
    const int nk   = K >> 5;

    float acc[2][8][4];
#pragma unroll
    for (int mi = 0; mi < 2; mi++)
#pragma unroll
        for (int ni = 0; ni < 8; ni++)
#pragma unroll
            for (int q = 0; q < 4; q++) acc[mi][ni][q] = 0.f;

    const int c0row = (t + 0)   >> 2, c0k = ((t + 0)   & 3) * 8;
    const int c1row = (t + 256) >> 2, c1k = ((t + 256) & 3) * 8;

    const __nv_bfloat16* gp[4] = {Ah, Al, Bh, Bl};

    auto issue = [&](int stage, int k0) {
#pragma unroll
        for (int m = 0; m < 4; m++) {
            int base = (m < 2) ? bm : bn;
            const __nv_bfloat16* g = gp[m];
            uint32_t so = sm_base + (uint32_t)(stage * 4 + m) * STG_H * 2;
            cp16(so + (uint32_t)(c0row * AST + c0k) * 2,
                 g + (size_t)(base + c0row) * K + k0 + c0k);
            cp16(so + (uint32_t)(c1row * AST + c1k) * 2,
                 g + (size_t)(base + c1row) * K + k0 + c1k);
        }
        asm volatile("cp.async.commit_group;");
    };

    issue(0, 0);

    for (int kt = 0; kt < nk; kt++) {
        if (kt + 1 < nk) {
            issue((kt + 1) & 1, (kt + 1) << 5);
            asm volatile("cp.async.wait_group 1;");
        } else {
            asm volatile("cp.async.wait_group 0;");
        }
        __syncthreads();

        const int stage = kt & 1;
        const uint32_t bAh = sm_base + (uint32_t)(stage * 4 + 0) * STG_H * 2;
        const uint32_t bAl = sm_base + (uint32_t)(stage * 4 + 1) * STG_H * 2;
        const uint32_t bBh = sm_base + (uint32_t)(stage * 4 + 2) * STG_H * 2;
        const uint32_t bBl = sm_base + (uint32_t)(stage * 4 + 3) * STG_H * 2;

#pragma unroll
        for (int ks = 0; ks < 2; ks++) {
            uint32_t ah[2][4], al[2][4], bh[8][2], bl[8][2];

            const int arow = wm * 32 + (lane & 15);
            const int acol = ks * 16 + (lane >> 4) * 8;
#pragma unroll
            for (int mi = 0; mi < 2; mi++) {
                uint32_t off = (uint32_t)((arow + mi * 16) * AST + acol) * 2;
                LDSM4(ah[mi], bAh + off);
                LDSM4(al[mi], bAl + off);
            }

            const int brow = wn * 64 + (lane >> 4) * 8 + (lane & 7);
            const int bcol = ks * 16 + ((lane >> 3) & 1) * 8;
#pragma unroll
            for (int ni2 = 0; ni2 < 4; ni2++) {
                uint32_t off = (uint32_t)((brow + ni2 * 16) * AST + bcol) * 2;
                uint32_t r[4];
                LDSM4(r, bBh + off);
                bh[ni2 * 2][0] = r[0]; bh[ni2 * 2][1] = r[1];
                bh[ni2 * 2 + 1][0] = r[2]; bh[ni2 * 2 + 1][1] = r[3];
                LDSM4(r, bBl + off);
                bl[ni2 * 2][0] = r[0]; bl[ni2 * 2][1] = r[1];
                bl[ni2 * 2 + 1][0] = r[2]; bl[ni2 * 2 + 1][1] = r[3];
            }

#pragma unroll
            for (int mi = 0; mi < 2; mi++)
#pragma unroll
                for (int ni = 0; ni < 8; ni++) {
                    MMA_BF16(acc[mi][ni], ah[mi], bh[ni]);
                    MMA_BF16(acc[mi][ni], al[mi], bh[ni]);
                    MMA_BF16(acc[mi][ni], ah[mi], bl[ni]);
                }
        }
        __syncthreads();
    }

#pragma unroll
    for (int mi = 0; mi < 2; mi++) {
        const int r0 = bm + wm * 32 + mi * 16 + (lane >> 2);
#pragma unroll
        for (int ni = 0; ni < 8; ni++) {
            const int col = bn + wn * 64 + ni * 8 + (lane & 3) * 2;
            float bx = bias[col], by = bias[col + 1];
            float2 v0 = make_float2(acc[mi][ni][0] + bx, acc[mi][ni][1] + by);
            float2 v1 = make_float2(acc[mi][ni][2] + bx, acc[mi][ni][3] + by);
            *(float2*)&C[(size_t)r0 * N + col] = v0;
            *(float2*)&C[(size_t)(r0 + 8) * N + col] = v1;
        }
    }
}

// ---------------------------------------------------------------------------
// Tensor-core flash attention.
// Block = (qtile 128 rows, h, b); 8 warps x 16 q-rows; BC=64, double-buffered.
// smem (bf16 halves, stride 72): Q hi/lo [128][72]; 2 bufs x {Kh,Kl,Vh,Vl}[64][72]
// ---------------------------------------------------------------------------
#define AT_ST 72
// byte offsets
#define Q_HI_B 0
#define Q_LO_B 18432
#define TILE_B 36864
#define MAT_B  9216
#define BUF_B  36864
#define ATT_SMEM 110592

__global__ __launch_bounds__(256)
void attn_mma(const float* __restrict__ bias, const unsigned char* __restrict__ mask,
              float* __restrict__ out,
              const __nv_bfloat16* __restrict__ Qh, const __nv_bfloat16* __restrict__ Ql,
              const __nv_bfloat16* __restrict__ Kh, const __nv_bfloat16* __restrict__ Kl,
              const __nv_bfloat16* __restrict__ Vh, const __nv_bfloat16* __restrict__ Vl)
{
    extern __shared__ __align__(16) __nv_bfloat16 smA[];
    const uint32_t s_base = (uint32_t)__cvta_generic_to_shared(smA);

    const int t = threadIdx.x, lane = t & 31, wid = t >> 5;
    const int qt = blockIdx.x, h = blockIdx.y, b = blockIdx.z;
    const int qbase = qt * 128;
    const size_t hb = (size_t)(b * NH + h) * SEQ * HD;

    const int lr7 = lane & 7, l8 = (lane >> 3) & 1, l16 = lane >> 4;

    const __nv_bfloat16* qsrc[2] = {Qh, Ql};
    const __nv_bfloat16* ksrc[4] = {Kh, Kl, Vh, Vl};

    // issue Q + tile0 (group 0)
#pragma unroll
    for (int it = 0; it < 8; it++) {
        int c = t + it * 256;
        int mat = c >> 10, r = (c >> 3) & 127, ck = c & 7;
        cp16(s_base + mat * Q_LO_B + (uint32_t)(r * AT_ST + ck * 8) * 2,
             qsrc[mat] + hb + (size_t)(qbase + r) * HD + ck * 8);
    }
#pragma unroll
    for (int it = 0; it < 8; it++) {
        int c = t + it * 256;
        int mat = c >> 9, r = (c >> 3) & 63, ck = c & 7;
        cp16(s_base + TILE_B + mat * MAT_B + (uint32_t)(r * AT_ST + ck * 8) * 2,
             ksrc[mat] + hb + (size_t)r * HD + ck * 8);
    }
    asm volatile("cp.async.commit_group;");
    // tile1 (group 1)
#pragma unroll
    for (int it = 0; it < 8; it++) {
        int c = t + it * 256;
        int mat = c >> 9, r = (c >> 3) & 63, ck = c & 7;
        cp16(s_base + TILE_B + BUF_B + mat * MAT_B + (uint32_t)(r * AT_ST + ck * 8) * 2,
             ksrc[mat] + hb + (size_t)(64 + r) * HD + ck * 8);
    }
    asm volatile("cp.async.commit_group;");
    asm volatile("cp.async.wait_group 1;");
    __syncthreads();

    // Q fragments, held in registers for the whole kernel
    uint32_t aqh[4][4], aql[4][4];
    {
        const int arow = wid * 16 + (lane & 15);
        const int acol = 8 * l16;
#pragma unroll
        for (int ks = 0; ks < 4; ks++) {
            uint32_t off = (uint32_t)(arow * AT_ST + ks * 16 + acol) * 2;
            LDSM4(aqh[ks], s_base + Q_HI_B + off);
            LDSM4(aql[ks], s_base + Q_LO_B + off);
        }
    }

    float O[8][4];
#pragma unroll
    for (int nf = 0; nf < 8; nf++)
#pragma unroll
        for (int q = 0; q < 4; q++) O[nf][q] = 0.f;
    float m0 = NEG, m1 = NEG, l0 = 0.f, l1 = 0.f;

    const float* bp = bias + (size_t)(b * NH + h) * SEQ * SEQ;
    const unsigned char* mrow = mask + (size_t)b * SEQ;
    const int qr = qbase + wid * 16 + (lane >> 2);
    const int colb = 2 * (lane & 3);

    const int krow = lr7 + 8 * l16;   // K b-frag row pattern
    const int kcol = 8 * l8;
    const int vrow = lr7 + 8 * l8;    // V trans row pattern
    const int vcol = 8 * l16;

    for (int kt = 0; kt < 16; kt++) {
        const uint32_t tb = s_base + TILE_B + (uint32_t)(kt & 1) * BUF_B;

        // prefetch bias + mask for this tile (hides DRAM behind MMAs)
        float2 bv0[8], bv1[8];
        uchar2 mk[8];
#pragma unroll
        for (int nf = 0; nf < 8; nf++) {
            int col = kt * 64 + nf * 8 + colb;
            bv0[nf] = *(const float2*)&bp[(size_t)qr * SEQ + col];
            bv1[nf] = *(const float2*)&bp[(size_t)(qr + 8) * SEQ + col];
            mk[nf]  = *(const uchar2*)&mrow[col];
        }

        // ---- S = Q K^T ----
        float s[8][4];
#pragma unroll
        for (int nf = 0; nf < 8; nf++)
#pragma unroll
            for (int q = 0; q < 4; q++) s[nf][q] = 0.f;

#pragma unroll
        for (int ks = 0; ks < 4; ks++) {
            uint32_t bh[8][2], bl[8][2];
#pragma unroll
            for (int nf2 = 0; nf2 < 4; nf2++) {
                uint32_t off = (uint32_t)((nf2 * 16 + krow) * AT_ST + ks * 16 + kcol) * 2;
                uint32_t r4[4];
                LDSM4(r4, tb + 0 * MAT_B + off);
                bh[2*nf2][0] = r4[0]; bh[2*nf2][1] = r4[1];
                bh[2*nf2+1][0] = r4[2]; bh[2*nf2+1][1] = r4[3];
                LDSM4(r4, tb + 1 * MAT_B + off);
                bl[2*nf2][0] = r4[0]; bl[2*nf2][1] = r4[1];
                bl[2*nf2+1][0] = r4[2]; bl[2*nf2+1][1] = r4[3];
            }
#pragma unroll
            for (int nf = 0; nf < 8; nf++) {
                MMA_BF16(s[nf], aqh[ks], bh[nf]);
                MMA_BF16(s[nf], aql[ks], bh[nf]);
                MMA_BF16(s[nf], aqh[ks], bl[nf]);
            }
        }

        // ---- bias + mask ----
#pragma unroll
        for (int nf = 0; nf < 8; nf++) {
            s[nf][0] = mk[nf].x ? NEG : s[nf][0] + bv0[nf].x;
            s[nf][1] = mk[nf].y ? NEG : s[nf][1] + bv0[nf].y;
            s[nf][2] = mk[nf].x ? NEG : s[nf][2] + bv1[nf].x;
            s[nf][3] = mk[nf].y ? NEG : s[nf][3] + bv1[nf].y;
        }

        // ---- online softmax (rows r and r+8) ----
        float mx0 = NEG, mx1 = NEG;
#pragma unroll
        for (int nf = 0; nf < 8; nf++) {
            mx0 = fmaxf(mx0, fmaxf(s[nf][0], s[nf][1]));
            mx1 = fmaxf(mx1, fmaxf(s[nf][2], s[nf][3]));
        }
        mx0 = fmaxf(mx0, __shfl_xor_sync(0xffffffffu, mx0, 1));
        mx0 = fmaxf(mx0, __shfl_xor_sync(0xffffffffu, mx0, 2));
        mx1 = fmaxf(mx1, __shfl_xor_sync(0xffffffffu, mx1, 1));
        mx1 = fmaxf(mx1, __shfl_xor_sync(0xffffffffu, mx1, 2));
        float mn0 = fmaxf(m0, mx0), mn1 = fmaxf(m1, mx1);
        float sc0 = __expf(m0 - mn0), sc1 = __expf(m1 - mn1);
        m0 = mn0; m1 = mn1;
        float su0 = 0.f, su1 = 0.f;
#pragma unroll
        for (int nf = 0; nf < 8; nf++) {
            s[nf][0] = __expf(s[nf][0] - mn0);
            s[nf][1] = __expf(s[nf][1] - mn0);
            s[nf][2] = __expf(s[nf][2] - mn1);
            s[nf][3] = __expf(s[nf][3] - mn1);
            su0 += s[nf][0] + s[nf][1];
            su1 += s[nf][2] + s[nf][3];
        }
        su0 += __shfl_xor_sync(0xffffffffu, su0, 1);
        su0 += __shfl_xor_sync(0xffffffffu, su0, 2);
        su1 += __shfl_xor_sync(0xffffffffu, su1, 1);
        su1 += __shfl_xor_sync(0xffffffffu, su1, 2);
        l0 = l0 * sc0 + su0;
        l1 = l1 * sc1 + su1;
#pragma unroll
        for (int nf = 0; nf < 8; nf++) {
            O[nf][0] *= sc0; O[nf][1] *= sc0;
            O[nf][2] *= sc1; O[nf][3] *= sc1;
        }

        // ---- O += P V  (P straight from S fragments, hi/lo split) ----
#pragma unroll
        for (int ks = 0; ks < 4; ks++) {
            uint32_t aph[4], apl[4];
            {
                const float* p0 = s[2 * ks];
                const float* p1 = s[2 * ks + 1];
                aph[0] = packbf(p0[0], p0[1]);
                aph[1] = packbf(p0[2], p0[3]);
                aph[2] = packbf(p1[0], p1[1]);
                aph[3] = packbf(p1[2], p1[3]);
                apl[0] = residpack(aph[0], p0[0], p0[1]);
                apl[1] = residpack(aph[1], p0[2], p0[3]);
                apl[2] = residpack(aph[2], p1[0], p1[1]);
                apl[3] = residpack(aph[3], p1[2], p1[3]);
            }
            uint32_t vh[8][2], vl[8][2];
#pragma unroll
            for (int nf2 = 0; nf2 < 4; nf2++) {
                uint32_t off = (uint32_t)((ks * 16 + vrow) * AT_ST + nf2 * 16 + vcol) * 2;
                uint32_t r4[4];
                LDSM4T(r4, tb + 2 * MAT_B + off);
                vh[2*nf2][0] = r4[0]; vh[2*nf2][1] = r4[1];
                vh[2*nf2+1][0] = r4[2]; vh[2*nf2+1][1] = r4[3];
                LDSM4T(r4, tb + 3 * MAT_B + off);
                vl[2*nf2][0] = r4[0]; vl[2*nf2][1] = r4[1];
                vl[2*nf2+1][0] = r4[2]; vl[2*nf2+1][1] = r4[3];
            }
#pragma unroll
            for (int nf = 0; nf < 8; nf++) {
                MMA_BF16(O[nf], aph, vh[nf]);
                MMA_BF16(O[nf], apl, vh[nf]);
                MMA_BF16(O[nf], aph, vl[nf]);
            }
        }

        __syncthreads();   // done reading buf (kt&1) before refill
        if (kt + 2 < 16) {
#pragma unroll
            for (int it = 0; it < 8; it++) {
                int c = t + it * 256;
                int mat = c >> 9, r = (c >> 3) & 63, ck = c & 7;
                cp16(s_base + TILE_B + (uint32_t)(kt & 1) * BUF_B + mat * MAT_B +
                         (uint32_t)(r * AT_ST + ck * 8) * 2,
                     ksrc[mat] + hb + (size_t)((kt + 2) * 64 + r) * HD + ck * 8);
            }
            asm volatile("cp.async.commit_group;");
        }
        if (kt + 1 < 16) {
            if (kt + 2 < 16) asm volatile("cp.async.wait_group 1;");
            else             asm volatile("cp.async.wait_group 0;");
            __syncthreads();
        }
    }

    // ---- epilogue ----
    float i0 = 1.f / l0, i1 = 1.f / l1;
    int orow = b * SEQ + qbase + wid * 16 + (lane >> 2);
#pragma unroll
    for (int nf = 0; nf < 8; nf++) {
        int col = h * HD + nf * 8 + colb;
        *(float2*)&out[(size_t)orow * EMB + col] =
            make_float2(O[nf][0] * i0, O[nf][1] * i0);
        *(float2*)&out[(size_t)(orow + 8) * EMB + col] =
            make_float2(O[nf][2] * i1, O[nf][3] * i1);
    }
}

// ---------------------------------------------------------------------------
extern "C" void kernel_launch(void* const* d_in, const int* in_sizes, int n_in,
                              void* d_out, int out_size)
{
    const float* query         = (const float*)d_in[0];
    const unsigned char* maskp = (const unsigned char*)d_in[1];
    const float* attn_bias     = (const float*)d_in[2];
    const float* Wqkv          = (const float*)d_in[3];
    const float* bqkv          = (const float*)d_in[4];
    const float* Wo            = (const float*)d_in[5];
    const float* bo            = (const float*)d_in[6];
    float* out                 = (float*)d_out;

    float *qkv, *att;
    __nv_bfloat16 *Ahi, *Alo, *W1hi, *W1lo, *W2hi, *W2lo, *Thi, *Tlo;
    __nv_bfloat16 *Qh, *Ql, *Kh, *Kl, *Vh, *Vl;
    cudaGetSymbolAddress((void**)&qkv,  g_qkv);
    cudaGetSymbolAddress((void**)&att,  g_att);
    cudaGetSymbolAddress((void**)&Ahi,  g_A_hi);
    cudaGetSymbolAddress((void**)&Alo,  g_A_lo);
    cudaGetSymbolAddress((void**)&W1hi, g_W1_hi);
    cudaGetSymbolAddress((void**)&W1lo, g_W1_lo);
    cudaGetSymbolAddress((void**)&W2hi, g_W2_hi);
    cudaGetSymbolAddress((void**)&W2lo, g_W2_lo);
    cudaGetSymbolAddress((void**)&Thi,  g_att_hi);
    cudaGetSymbolAddress((void**)&Tlo,  g_att_lo);
    cudaGetSymbolAddress((void**)&Qh,   g_Qh);
    cudaGetSymbolAddress((void**)&Ql,   g_Ql);
    cudaGetSymbolAddress((void**)&Kh,   g_Kh);
    cudaGetSymbolAddress((void**)&Kl,   g_Kl);
    cudaGetSymbolAddress((void**)&Vh,   g_Vh);
    cudaGetSymbolAddress((void**)&Vl,   g_Vl);

    const size_t gemm_smem = 8 * (size_t)STG_H * 2;   // 81920 B
    cudaFuncSetAttribute(gemm_mma,
                         cudaFuncAttributeMaxDynamicSharedMemorySize, (int)gemm_smem);
    cudaFuncSetAttribute(attn_mma,
                         cudaFuncAttributeMaxDynamicSharedMemorySize, ATT_SMEM);

    // 0) split inputs + weights into bf16 (hi, lo)
    split_kernel<<<(MTOT * EMB) / 1024, 256>>>(query, Ahi, Alo, MTOT * EMB);
    split_kernel<<<(3 * EMB * EMB) / 1024, 256>>>(Wqkv, W1hi, W1lo, 3 * EMB * EMB);
    split_kernel<<<(EMB * EMB) / 1024, 256>>>(Wo, W2hi, W2lo, EMB * EMB);

    // 1) QKV projection
    {
        dim3 grid(3 * EMB / 128, MTOT / 128);
        gemm_mma<<<grid, 256, gemm_smem>>>(Ahi, Alo, W1hi, W1lo, bqkv, qkv,
                                           MTOT, 3 * EMB, EMB);
    }

    // 2) re-layout qkv -> head-major bf16 hi/lo (Q pre-scaled)
    {
        dim3 grid((MTOT * EMB) / 1024, 3);
        qkv_split<<<grid, 256>>>(qkv, Qh, Ql, Kh, Kl, Vh, Vl);
    }

    // 3) tensor-core flash attention
    {
        dim3 grid(SEQ / 128, NH, BATCH);
        attn_mma<<<grid, 256, ATT_SMEM>>>(attn_bias, maskp, att,
                                          Qh, Ql, Kh, Kl, Vh, Vl);
    }

    // 4) split attention output, output projection
    split_kernel<<<(MTOT * EMB) / 1024, 256>>>(att, Thi, Tlo, MTOT * EMB);
    {
        dim3 grid(EMB / 128, MTOT / 128);
        gemm_mma<<<grid, 256, gemm_smem>>>(Thi, Tlo, W2hi, W2lo, bo, out,
                                           MTOT, EMB, EMB);
    }
}